// round 11
// baseline (speedup 1.0000x reference)
#include <cuda_runtime.h>
#include <math.h>

#define BB 32
typedef unsigned long long ull;

// ---------------- scratch ----------------
__device__ float g_x    [BB*512*512];   // x[b][n][h*64+o]
__device__ float g_Wh2  [BB*512*64];
__device__ float g_s2src[BB*512];
__device__ float g_s2dst[BB*512];
__device__ float g_z    [BB*512*64];
__device__ float g_part [256*BB*256];   // fc1 split-K partials [split][b*256+c]
__device__ float g_fc1acc[BB*256];

// f32x2 packed helpers
__device__ __forceinline__ ull pk2(float lo, float hi) {
    ull r;
    asm("mov.b64 %0, {%1, %2};" : "=l"(r) : "f"(lo), "f"(hi));
    return r;
}
__device__ __forceinline__ void upk2(ull v, float& lo, float& hi) {
    asm("mov.b64 {%0, %1}, %2;" : "=f"(lo), "=f"(hi) : "l"(v));
}
__device__ __forceinline__ ull fma2(ull a, ull b, ull c) {
    ull d;
    asm("fma.rn.f32x2 %0, %1, %2, %3;" : "=l"(d) : "l"(a), "l"(b), "l"(c));
    return d;
}

// ================= kG1 v2: fused GEMM + GAT layer1, per (b,h,dim-half) =================
// smem floats (all offsets in floats):
//   [0,16384)      sWh [512][32]
//   [16384,16896)  sd
//   [16896,17408)  ssrc
//   [17408,25600)  phase A: sW 4096 | sF 4096     (aliased by phase B aux below)
//   phase B aux @17408: Bv 512, bv 512, rA 512, ra 512, rIZ 512,
//                       sp 512, rIdx 512, rm 512 (int), cum 514, cnt 513 (int),
//                       segT 1024, zSB 513, zPb 513, ztot 32   (= 7203 <= 8192)
#define G1_SMEM_FLOATS 25600

__global__ __launch_bounds__(512, 2) void kG1(const float* __restrict__ state,
                                              const float* __restrict__ W_heads,
                                              const float* __restrict__ a_src,
                                              const float* __restrict__ a_dst) {
    extern __shared__ float sm[];
    float* sWh  = sm;                   // 16384
    float* sd   = sm + 16384;           // 512
    float* ssrc = sm + 16896;           // 512
    float* sW   = sm + 17408;           // 4096 (phase A)
    float* sF   = sm + 21504;           // 4096 (phase A)
    // phase B aux (aliases sW/sF):
    float* Bv   = sm + 17408;
    float* bv   = Bv + 512;
    float* rA   = bv + 512;
    float* ra   = rA + 512;
    float* rIZ  = ra + 512;
    int*   sp   = (int*)(rIZ + 512);
    int*   rIdx = sp + 512;
    int*   rm   = rIdx + 512;
    int*   cum  = rm + 512;             // 514
    int*   cnt  = cum + 514;            // 513
    float* segT = (float*)(cnt + 513);  // 1024
    float* zSB  = segT + 1024;          // 513
    float* zPb  = zSB + 513;            // 513
    float* ztot = zPb + 513;            // 32

    int tid = threadIdx.x;
    int bh   = blockIdx.x >> 1;
    int half = blockIdx.x & 1;
    int b = bh >> 3, h = bh & 7;

    int tc = tid & 15, tr = tid >> 4;   // tc 0..15, tr 0..31
    int c0 = tc*4, r0 = tr*2;
    int storeHalf = ((tc >> 3) == half);

    float4 vsrc = *(const float4*)(a_src + h*64 + c0);
    float4 vdst = *(const float4*)(a_dst + h*64 + c0);

    // load W_heads[h] (64x64) into sW
    for (int i = tid; i < 1024; i += 512)
        ((float4*)sW)[i] = ((const float4*)(W_heads + h*4096))[i];

    // GEMM over 8 chunks of 64 rows; fused s-dots from accumulators
    for (int cc = 0; cc < 8; cc++) {
        __syncthreads();
        for (int i = tid; i < 1024; i += 512)
            ((float4*)sF)[i] = ((const float4*)(state + (size_t)b*32768 + cc*4096))[i];
        __syncthreads();
        float4 a0 = {0,0,0,0}, a1 = a0;
        #pragma unroll 16
        for (int f = 0; f < 64; f++) {
            float4 w = ((float4*)(sW + f*64))[tc];
            float x0 = sF[(r0+0)*64+f];
            float x1 = sF[(r0+1)*64+f];
            a0.x += x0*w.x; a0.y += x0*w.y; a0.z += x0*w.z; a0.w += x0*w.w;
            a1.x += x1*w.x; a1.y += x1*w.y; a1.z += x1*w.z; a1.w += x1*w.w;
        }
        int nb = cc*64 + r0;
        if (storeHalf) {
            ((float4*)(sWh + (nb+0)*32))[tc & 7] = a0;
            ((float4*)(sWh + (nb+1)*32))[tc & 7] = a1;
        }
        float s0 = a0.x*vsrc.x + a0.y*vsrc.y + a0.z*vsrc.z + a0.w*vsrc.w;
        float s1 = a1.x*vsrc.x + a1.y*vsrc.y + a1.z*vsrc.z + a1.w*vsrc.w;
        float d0 = a0.x*vdst.x + a0.y*vdst.y + a0.z*vdst.z + a0.w*vdst.w;
        float d1 = a1.x*vdst.x + a1.y*vdst.y + a1.z*vdst.z + a1.w*vdst.w;
        #pragma unroll
        for (int off = 8; off; off >>= 1) {
            s0 += __shfl_xor_sync(0xffffffffu, s0, off);
            s1 += __shfl_xor_sync(0xffffffffu, s1, off);
            d0 += __shfl_xor_sync(0xffffffffu, d0, off);
            d1 += __shfl_xor_sync(0xffffffffu, d1, off);
        }
        if (tc == 0) {
            ssrc[nb+0] = s0; ssrc[nb+1] = s1;
            sd[nb+0]   = d0; sd[nb+1]   = d1;
        }
    }
    __syncthreads();
    sp[tid] = tid;
    __syncthreads();

    // bitonic sort ascending on sd with permutation sp
    for (int k = 2; k <= 512; k <<= 1) {
        for (int j = k >> 1; j > 0; j >>= 1) {
            int ixj = tid ^ j;
            if (ixj > tid) {
                float a = sd[tid], c = sd[ixj];
                bool up = ((tid & k) == 0);
                if ((a > c) == up) {
                    sd[tid] = c; sd[ixj] = a;
                    int t2 = sp[tid]; sp[tid] = sp[ixj]; sp[ixj] = t2;
                }
            }
            __syncthreads();
        }
    }
    { float d = sd[tid]; Bv[tid] = expf(d); bv[tid] = expf(0.2f*d); }
    cnt[tid] = 0; if (tid == 0) cnt[512] = 0;
    __syncthreads();

    // normalizer scans: 16 segments of 32
    if (tid < 32) {
        int which = tid >> 4, sg = tid & 15; float acc = 0.f;
        for (int u = 0; u < 32; u++) { int t = sg*32+u; acc += which ? Bv[t] : bv[t]; }
        ztot[tid] = acc;
    }
    __syncthreads();
    if (tid < 32) {
        int which = tid >> 4, sg = tid & 15; float acc = 0.f;
        if (!which) {
            for (int s2 = 0; s2 < sg; s2++) acc += ztot[s2];
            for (int u = 0; u < 32; u++) { int t = sg*32+u; zPb[t] = acc; acc += bv[t]; }
            if (sg == 15) zPb[512] = acc;
        } else {
            for (int s2 = sg+1; s2 < 16; s2++) acc += ztot[16+s2];
            for (int u = 31; u >= 0; u--) { int t = sg*32+u; acc += Bv[t]; zSB[t] = acc; }
            if (sg == 15) zSB[512] = 0.f;
        }
    }
    __syncthreads();

    // per-row threshold m, factors, 1/Z, histogram
    {
        float s = ssrc[tid], thr = -s;
        int lo = 0, hi = 512;
        while (lo < hi) { int mid = (lo+hi) >> 1; if (sd[mid] > thr) hi = mid; else lo = mid+1; }
        int m = lo;
        float A = expf(s), af = expf(0.2f*s);
        rA[tid] = A; ra[tid] = af;
        rIZ[tid] = 1.f / (A*zSB[m] + af*zPb[m]);
        rm[tid] = m;
        atomicAdd(&cnt[m], 1);
    }
    __syncthreads();
    if (tid < 32) {
        int start = tid*17, end = min(513, start+17);
        int s = 0;
        for (int i = start; i < end; i++) s += cnt[i];
        int v = s;
        #pragma unroll
        for (int off = 1; off < 32; off <<= 1) {
            int u = __shfl_up_sync(0xffffffffu, v, off);
            if (tid >= off) v += u;
        }
        int run = v - s;
        for (int i = start; i < end; i++) { cum[i] = run; run += cnt[i]; }
        if (start < 513 && end == 513) cum[513] = run;
    }
    __syncthreads();
    cnt[tid] = 0; if (tid == 0) cnt[512] = 0;
    __syncthreads();
    { int m = rm[tid]; int pos = cum[m] + atomicAdd(&cnt[m], 1); rIdx[pos] = tid; }
    __syncthreads();

    int dim = tid & 31, seg = tid >> 5;    // 16 segments x 32 dims
    {
        float tB = 0.f, tb = 0.f; int base = seg*32;
        #pragma unroll 8
        for (int u = 0; u < 32; u++) {
            int t = base + u; float w = sWh[sp[t]*32 + dim];
            tB += Bv[t]*w; tb += bv[t]*w;
        }
        segT[seg*32+dim] = tB; segT[512+seg*32+dim] = tb;
    }
    __syncthreads();
    {
        float* outB = g_x + (size_t)b*262144 + h*64 + half*32;
        float accB = 0.f, accb = 0.f, tTb = 0.f;
        for (int s2 = 0; s2 < 16; s2++) {
            float vB = segT[s2*32+dim], vb = segT[512+s2*32+dim];
            if (s2 > seg) { accB += vB; accb += vb; }
            tTb += vb;
        }
        if (seg == 15) {
            for (int idx = cum[512]; idx < cum[513]; idx++) {
                int r = rIdx[idx];
                float val = (rA[r]*accB + ra[r]*(tTb - accb)) * rIZ[r];
                val = val > 0.f ? val : expf(val) - 1.f;
                outB[r*512 + dim] = val;
            }
        }
        int base = seg*32;
        for (int u = 31; u >= 0; u--) {
            int t = base + u;
            float w = sWh[sp[t]*32 + dim];
            accB += Bv[t]*w; accb += bv[t]*w;
            for (int idx = cum[t]; idx < cum[t+1]; idx++) {
                int r = rIdx[idx];
                float val = (rA[r]*accB + ra[r]*(tTb - accb)) * rIZ[r];
                val = val > 0.f ? val : expf(val) - 1.f;
                outB[r*512 + dim] = val;
            }
        }
    }
}

// ================= kC: Wh2 = x @ W_out, fused s2 dots (R8 scalar version) =================
__global__ __launch_bounds__(256) void kC(const float* __restrict__ W_out,
                                          const float* __restrict__ aos,
                                          const float* __restrict__ aod) {
    __shared__ float sX[4096];
    __shared__ float sW[4096];
    int b = blockIdx.x, nc = blockIdx.y;
    int tid = threadIdx.x;
    int tc = tid & 15, tr = tid >> 4;
    int r0 = tr*4;
    float4 a0 = {0,0,0,0}, a1 = a0, a2 = a0, a3 = a0;
    const float* xbase = g_x + (size_t)(b*512 + nc*64)*512;
    for (int kc = 0; kc < 8; kc++) {
        __syncthreads();
        for (int i = tid; i < 1024; i += 256) {
            int n = i >> 4, c4 = i & 15;
            ((float4*)sX)[i] = *(const float4*)(xbase + (size_t)n*512 + kc*64 + c4*4);
        }
        for (int i = tid; i < 1024; i += 256)
            ((float4*)sW)[i] = ((const float4*)(W_out + kc*4096))[i];
        __syncthreads();
        #pragma unroll 8
        for (int f = 0; f < 64; f++) {
            float4 w = ((float4*)(sW + f*64))[tc];
            float x0 = sX[(r0+0)*64+f];
            float x1 = sX[(r0+1)*64+f];
            float x2 = sX[(r0+2)*64+f];
            float x3 = sX[(r0+3)*64+f];
            a0.x += x0*w.x; a0.y += x0*w.y; a0.z += x0*w.z; a0.w += x0*w.w;
            a1.x += x1*w.x; a1.y += x1*w.y; a1.z += x1*w.z; a1.w += x1*w.w;
            a2.x += x2*w.x; a2.y += x2*w.y; a2.z += x2*w.z; a2.w += x2*w.w;
            a3.x += x3*w.x; a3.y += x3*w.y; a3.z += x3*w.z; a3.w += x3*w.w;
        }
    }
    __syncthreads();
    float* sO = sX;
    ((float4*)(sO + (r0+0)*64))[tc] = a0;
    ((float4*)(sO + (r0+1)*64))[tc] = a1;
    ((float4*)(sO + (r0+2)*64))[tc] = a2;
    ((float4*)(sO + (r0+3)*64))[tc] = a3;
    float* wo = g_Wh2 + (size_t)(b*512 + nc*64 + r0)*64;
    ((float4*)(wo +   0))[tc] = a0;
    ((float4*)(wo +  64))[tc] = a1;
    ((float4*)(wo + 128))[tc] = a2;
    ((float4*)(wo + 192))[tc] = a3;
    __syncthreads();
    {
        int w = tid >> 5, lane = tid & 31;
        float as0 = aos[lane], as1 = aos[32+lane];
        float ad0 = aod[lane], ad1 = aod[32+lane];
        for (int n = w*8; n < w*8+8; n++) {
            float v0 = sO[n*64+lane], v1 = sO[n*64+32+lane];
            float ss = v0*as0 + v1*as1;
            float dd = v0*ad0 + v1*ad1;
            #pragma unroll
            for (int off = 16; off; off >>= 1) {
                ss += __shfl_xor_sync(0xffffffffu, ss, off);
                dd += __shfl_xor_sync(0xffffffffu, dd, off);
            }
            if (lane == 0) {
                g_s2src[b*512 + nc*64 + n] = ss;
                g_s2dst[b*512 + nc*64 + n] = dd;
            }
        }
    }
}

// ================= kG2: GAT layer2 (per b, dim-quarter of 16) — R8 version =================
#define G2_SMEM_FLOATS (8192 + 3584 + 1536 + 1027 + 1024 + 1026 + 64)

__global__ __launch_bounds__(512) void kG2() {
    extern __shared__ float sm[];
    float* sWh  = sm;                 // 8192 : [n][16]
    float* sd   = sm + 8192;
    float* Bv   = sd + 512;
    float* bv   = Bv + 512;
    float* ssrc = bv + 512;
    float* rA   = ssrc + 512;
    float* ra   = rA + 512;
    float* rIZ  = ra + 512;
    int*   sp   = (int*)(rIZ + 512);
    int*   rIdx = sp + 512;
    int*   rm   = rIdx + 512;
    int*   cum  = rm + 512;
    int*   cnt  = cum + 514;
    float* segT = (float*)(cnt + 513);   // 1024
    float* zSB  = segT + 1024;
    float* zPb  = zSB + 513;
    float* ztot = zPb + 513;             // 64

    int tid = threadIdx.x;
    int b = blockIdx.x >> 2, q = blockIdx.x & 3;

    for (int i = tid; i < 2048; i += 512) {
        int n = i >> 2, c4 = i & 3;
        ((float4*)sWh)[i] = *(const float4*)(g_Wh2 + (size_t)b*32768 + n*64 + q*16 + c4*4);
    }
    sd[tid]   = g_s2dst[b*512 + tid];
    ssrc[tid] = g_s2src[b*512 + tid];
    sp[tid]   = tid;
    __syncthreads();

    for (int k = 2; k <= 512; k <<= 1) {
        for (int j = k >> 1; j > 0; j >>= 1) {
            int ixj = tid ^ j;
            if (ixj > tid) {
                float a = sd[tid], c = sd[ixj];
                bool up = ((tid & k) == 0);
                if ((a > c) == up) {
                    sd[tid] = c; sd[ixj] = a;
                    int t2 = sp[tid]; sp[tid] = sp[ixj]; sp[ixj] = t2;
                }
            }
            __syncthreads();
        }
    }
    { float d = sd[tid]; Bv[tid] = expf(d); bv[tid] = expf(0.2f*d); }
    cnt[tid] = 0; if (tid == 0) cnt[512] = 0;
    __syncthreads();

    if (tid < 64) {
        int which = tid >> 5, sg = tid & 31; float acc = 0.f;
        for (int u = 0; u < 16; u++) { int t = sg*16+u; acc += which ? Bv[t] : bv[t]; }
        ztot[which*32 + sg] = acc;
    }
    __syncthreads();
    if (tid < 64) {
        int which = tid >> 5, sg = tid & 31; float acc = 0.f;
        if (!which) {
            for (int s2 = 0; s2 < sg; s2++) acc += ztot[s2];
            for (int u = 0; u < 16; u++) { int t = sg*16+u; zPb[t] = acc; acc += bv[t]; }
            if (sg == 31) zPb[512] = acc;
        } else {
            for (int s2 = sg+1; s2 < 32; s2++) acc += ztot[32+s2];
            for (int u = 15; u >= 0; u--) { int t = sg*16+u; acc += Bv[t]; zSB[t] = acc; }
            if (sg == 31) zSB[512] = 0.f;
        }
    }
    __syncthreads();

    {
        float s = ssrc[tid], thr = -s;
        int lo = 0, hi = 512;
        while (lo < hi) { int mid = (lo+hi) >> 1; if (sd[mid] > thr) hi = mid; else lo = mid+1; }
        int m = lo;
        float A = expf(s), af = expf(0.2f*s);
        rA[tid] = A; ra[tid] = af;
        rIZ[tid] = 1.f / (A*zSB[m] + af*zPb[m]);
        rm[tid] = m;
        atomicAdd(&cnt[m], 1);
    }
    __syncthreads();
    if (tid < 32) {
        int start = tid*17, end = min(513, start+17);
        int s = 0;
        for (int i = start; i < end; i++) s += cnt[i];
        int v = s;
        #pragma unroll
        for (int off = 1; off < 32; off <<= 1) {
            int u = __shfl_up_sync(0xffffffffu, v, off);
            if (tid >= off) v += u;
        }
        int run = v - s;
        for (int i = start; i < end; i++) { cum[i] = run; run += cnt[i]; }
        if (start < 513 && end == 513) cum[513] = run;
    }
    __syncthreads();
    cnt[tid] = 0; if (tid == 0) cnt[512] = 0;
    __syncthreads();
    { int m = rm[tid]; int pos = cum[m] + atomicAdd(&cnt[m], 1); rIdx[pos] = tid; }
    __syncthreads();

    int dim = tid & 15, seg = tid >> 4;     // 32 segments x 16 dims
    {
        float tB = 0.f, tb = 0.f; int base = seg*16;
        #pragma unroll 8
        for (int u = 0; u < 16; u++) {
            int t = base + u; float w = sWh[sp[t]*16 + dim];
            tB += Bv[t]*w; tb += bv[t]*w;
        }
        segT[seg*16+dim] = tB; segT[512+seg*16+dim] = tb;
    }
    __syncthreads();
    {
        float* outB = g_z + (size_t)b*32768 + q*16;
        float accB = 0.f, accb = 0.f, tTb = 0.f;
        for (int s2 = 0; s2 < 32; s2++) {
            float vB = segT[s2*16+dim], vb = segT[512+s2*16+dim];
            if (s2 > seg) { accB += vB; accb += vb; }
            tTb += vb;
        }
        if (seg == 31) {
            for (int idx = cum[512]; idx < cum[513]; idx++) {
                int r = rIdx[idx];
                float val = (rA[r]*accB + ra[r]*(tTb - accb)) * rIZ[r];
                outB[r*64 + dim] = val;
            }
        }
        int base = seg*16;
        for (int u = 15; u >= 0; u--) {
            int t = base + u;
            float w = sWh[sp[t]*16 + dim];
            accB += Bv[t]*w; accb += bv[t]*w;
            for (int idx = cum[t]; idx < cum[t+1]; idx++) {
                int r = rIdx[idx];
                float val = (rA[r]*accB + ra[r]*(tTb - accb)) * rIZ[r];
                outB[r*64 + dim] = val;
            }
        }
    }
}

// ================= kE v4: fc1 split-K x split-rows streamer =================
__global__ __launch_bounds__(256) void kE(const float* __restrict__ fc1_w) {
    __shared__ __align__(16) ull sZd[16*128];   // packed (z,z), 16KB
    int tid = threadIdx.x;
    int split = blockIdx.x >> 1;
    int rh = blockIdx.x & 1;
    int k0 = split * 128;
    int cq = tid & 63;
    int rg = tid >> 6;                  // 0..3

    for (int i = tid; i < 2048; i += 256) {
        int r = i >> 7, k = i & 127;
        float v = g_z[(size_t)(rh*16 + r)*32768 + k0 + k];
        sZd[i] = pk2(v, v);
    }
    __syncthreads();

    ull acc[4][2];
    ull zero = pk2(0.f, 0.f);
    #pragma unroll
    for (int r = 0; r < 4; r++) { acc[r][0] = zero; acc[r][1] = zero; }

    const float* Wp = fc1_w + (size_t)k0*256 + cq*4;
    const ull* zp = &sZd[rg*4*128];
    #pragma unroll 4
    for (int k = 0; k < 128; k++) {
        float4 w = *(const float4*)(Wp + (size_t)k*256);
        ull w01 = pk2(w.x, w.y);
        ull w23 = pk2(w.z, w.w);
        #pragma unroll
        for (int r = 0; r < 4; r++) {
            ull zz = zp[r*128 + k];
            acc[r][0] = fma2(zz, w01, acc[r][0]);
            acc[r][1] = fma2(zz, w23, acc[r][1]);
        }
    }

    float* outp = g_part + (size_t)split*8192 + rh*16*256;
    #pragma unroll
    for (int r = 0; r < 4; r++) {
        float4 v;
        upk2(acc[r][0], v.x, v.y);
        upk2(acc[r][1], v.z, v.w);
        *(float4*)(outp + (rg*4 + r)*256 + cq*4) = v;
    }
}

// ================= kR: reduce 256 split-partials -> g_fc1acc =================
__global__ __launch_bounds__(256) void kR() {
    __shared__ float red[256];
    int b = blockIdx.x >> 3, cs = blockIdx.x & 7;
    int tid = threadIdx.x;
    int cl = tid & 31, sg = tid >> 5;
    const float* pp = g_part + (size_t)(sg*32)*8192 + b*256 + cs*32 + cl;
    float a = 0.f;
    #pragma unroll 8
    for (int s = 0; s < 32; s++) a += pp[(size_t)s*8192];
    red[tid] = a;
    __syncthreads();
    if (tid < 32) {
        float t = red[tid];
        #pragma unroll
        for (int j = 1; j < 8; j++) t += red[j*32 + tid];
        g_fc1acc[b*256 + cs*32 + tid] = t;
    }
}

// ================= kF: bias+relu, fc2, fc3, tanh =================
__global__ __launch_bounds__(256) void kF(const float* __restrict__ fc1_b, const float* __restrict__ fc2_w,
                   const float* __restrict__ fc2_b, const float* __restrict__ fc3_w,
                   const float* __restrict__ fc3_b, float* __restrict__ out) {
    int b = blockIdx.x; int tid = threadIdx.x;
    __shared__ float s1[256], s2[256];
    s1[tid] = fmaxf(g_fc1acc[b*256 + tid] + fc1_b[tid], 0.f);
    __syncthreads();
    float acc = fc2_b[tid];
    #pragma unroll 8
    for (int k2 = 0; k2 < 256; k2++) acc += s1[k2] * fc2_w[k2*256 + tid];
    s2[tid] = fmaxf(acc, 0.f);
    __syncthreads();
    if (tid < 4) {
        float a3 = fc3_b[tid];
        for (int k2 = 0; k2 < 256; k2++) a3 += s2[k2] * fc3_w[k2*4 + tid];
        out[b*4 + tid] = tanhf(a3);
    }
}

extern "C" void kernel_launch(void* const* d_in, const int* in_sizes, int n_in,
                              void* d_out, int out_size) {
    const float* state     = (const float*)d_in[0];
    const float* W_heads   = (const float*)d_in[1];
    const float* a_src     = (const float*)d_in[2];
    const float* a_dst     = (const float*)d_in[3];
    const float* W_out     = (const float*)d_in[4];
    const float* a_out_src = (const float*)d_in[5];
    const float* a_out_dst = (const float*)d_in[6];
    const float* fc1_w     = (const float*)d_in[7];
    const float* fc1_b     = (const float*)d_in[8];
    const float* fc2_w     = (const float*)d_in[9];
    const float* fc2_b     = (const float*)d_in[10];
    const float* fc3_w     = (const float*)d_in[11];
    const float* fc3_b     = (const float*)d_in[12];
    float* out = (float*)d_out;

    const int SM1 = G1_SMEM_FLOATS * 4;
    const int SM2 = G2_SMEM_FLOATS * 4;
    static int inited = 0;
    if (!inited) {
        cudaFuncSetAttribute(kG1, cudaFuncAttributeMaxDynamicSharedMemorySize, SM1);
        cudaFuncSetAttribute(kG2, cudaFuncAttributeMaxDynamicSharedMemorySize, SM2);
        inited = 1;
    }

    kG1<<<512, 512, SM1>>>(state, W_heads, a_src, a_dst);
    kC <<<dim3(32, 8), 256>>>(W_out, a_out_src, a_out_dst);
    kG2<<<128, 512, SM2>>>();
    kE <<<512, 256>>>(fc1_w);
    kR <<<256, 256>>>();
    kF <<<32, 256>>>(fc1_b, fc2_w, fc2_b, fc3_w, fc3_b, out);
}

// round 12
// speedup vs baseline: 1.2592x; 1.2592x over previous
#include <cuda_runtime.h>
#include <math.h>

#define BB 32
typedef unsigned long long ull;

// ---------------- scratch ----------------
__device__ float g_x    [BB*512*512];   // x[b][n][h*64+o]
__device__ float g_Wh2  [BB*512*64];
__device__ float g_s2src[BB*512];
__device__ float g_s2dst[BB*512];
__device__ float g_z    [BB*512*64];
__device__ float g_part [256*BB*256];   // fc1 split-K partials [split][b*256+c]
__device__ float g_fc1acc[BB*256];

// f32x2 packed helpers
__device__ __forceinline__ ull pk2(float lo, float hi) {
    ull r;
    asm("mov.b64 %0, {%1, %2};" : "=l"(r) : "f"(lo), "f"(hi));
    return r;
}
__device__ __forceinline__ void upk2(ull v, float& lo, float& hi) {
    asm("mov.b64 {%0, %1}, %2;" : "=f"(lo), "=f"(hi) : "l"(v));
}
__device__ __forceinline__ ull fma2(ull a, ull b, ull c) {
    ull d;
    asm("fma.rn.f32x2 %0, %1, %2, %3;" : "=l"(d) : "l"(a), "l"(b), "l"(c));
    return d;
}

// ================= kG1: fused feat@W_heads + GAT layer1 (per b,h) =================
// smem floats: sWh 32768 | work (sWt 4224 + sF 8192) | aux as R8
#define G1_SMEM_FLOATS (32768 + 12416 + 3584 + 1536 + 1027 + 1024 + 1026 + 16)

__global__ __launch_bounds__(512) void kG1(const float* __restrict__ state,
                                           const float* __restrict__ W_heads,
                                           const float* __restrict__ a_src,
                                           const float* __restrict__ a_dst) {
    extern __shared__ float sm[];
    float* sWh  = sm;                 // 32768
    float* work = sm + 32768;         // 12416
    float* sd   = sm + 45184;
    float* Bv   = sd + 512;
    float* bv   = Bv + 512;
    float* ssrc = bv + 512;
    float* rA   = ssrc + 512;
    float* ra   = rA + 512;
    float* rIZ  = ra + 512;
    int*   sp   = (int*)(rIZ + 512);
    int*   rIdx = sp + 512;
    int*   rm   = rIdx + 512;
    int*   cum  = rm + 512;           // 514
    int*   cnt  = cum + 514;          // 513
    float* segT = (float*)(cnt + 513);// 1024
    float* zSB  = segT + 1024;        // 513
    float* zPb  = zSB + 513;          // 513
    float* ztot = zPb + 513;          // 16

    int tid = threadIdx.x;
    int b = blockIdx.x >> 3, h = blockIdx.x & 7;
    float* sWt = work;                // transposed [c][f], stride 66 (4224)
    float* sF  = work + 4224;         // 8192 (128 rows x 64)

    // load & transpose W_heads[h]: sWt[c][f]
    for (int i = tid; i < 1024; i += 512) {
        float4 w = ((const float4*)(W_heads + h*4096))[i];
        int f = i >> 4, c4 = (i & 15)*4;
        sWt[(c4+0)*66 + f] = w.x;
        sWt[(c4+1)*66 + f] = w.y;
        sWt[(c4+2)*66 + f] = w.z;
        sWt[(c4+3)*66 + f] = w.w;
    }

    int tc = tid & 15, tr = tid >> 4;      // tc 0..15, tr 0..31
    int r0 = tr*4;
    const float* wp0 = sWt + (tc     )*66; // banks 2*tc — conflict-free
    const float* wp1 = sWt + (tc + 16)*66;
    const float* wp2 = sWt + (tc + 32)*66;
    const float* wp3 = sWt + (tc + 48)*66;

    for (int cc = 0; cc < 4; cc++) {
        __syncthreads();
        for (int i = tid; i < 2048; i += 512)
            ((float4*)sF)[i] = ((const float4*)(state + (size_t)b*32768 + cc*8192))[i];
        __syncthreads();
        ull acc[4][4];
        ull zero = pk2(0.f, 0.f);
        #pragma unroll
        for (int r = 0; r < 4; r++)
            #pragma unroll
            for (int c = 0; c < 4; c++) acc[r][c] = zero;
        #pragma unroll 8
        for (int f = 0; f < 64; f += 2) {
            ull x0 = *(const ull*)&sF[(r0+0)*64+f];
            ull x1 = *(const ull*)&sF[(r0+1)*64+f];
            ull x2 = *(const ull*)&sF[(r0+2)*64+f];
            ull x3 = *(const ull*)&sF[(r0+3)*64+f];
            ull w0 = *(const ull*)&wp0[f];
            ull w1 = *(const ull*)&wp1[f];
            ull w2 = *(const ull*)&wp2[f];
            ull w3 = *(const ull*)&wp3[f];
            acc[0][0] = fma2(x0,w0,acc[0][0]); acc[0][1] = fma2(x0,w1,acc[0][1]);
            acc[0][2] = fma2(x0,w2,acc[0][2]); acc[0][3] = fma2(x0,w3,acc[0][3]);
            acc[1][0] = fma2(x1,w0,acc[1][0]); acc[1][1] = fma2(x1,w1,acc[1][1]);
            acc[1][2] = fma2(x1,w2,acc[1][2]); acc[1][3] = fma2(x1,w3,acc[1][3]);
            acc[2][0] = fma2(x2,w0,acc[2][0]); acc[2][1] = fma2(x2,w1,acc[2][1]);
            acc[2][2] = fma2(x2,w2,acc[2][2]); acc[2][3] = fma2(x2,w3,acc[2][3]);
            acc[3][0] = fma2(x3,w0,acc[3][0]); acc[3][1] = fma2(x3,w1,acc[3][1]);
            acc[3][2] = fma2(x3,w2,acc[3][2]); acc[3][3] = fma2(x3,w3,acc[3][3]);
        }
        int nb = cc*128 + r0;
        #pragma unroll
        for (int r = 0; r < 4; r++) {
            #pragma unroll
            for (int c = 0; c < 4; c++) {
                float lo, hi; upk2(acc[r][c], lo, hi);
                sWh[(nb+r)*64 + tc + 16*c] = lo + hi;
            }
        }
    }
    __syncthreads();

    {
        int w = tid >> 5, lane = tid & 31;
        float as0 = a_src[h*64+lane], as1 = a_src[h*64+32+lane];
        float ad0 = a_dst[h*64+lane], ad1 = a_dst[h*64+32+lane];
        for (int n = w*32; n < w*32+32; n++) {
            float v0 = sWh[n*64+lane], v1 = sWh[n*64+32+lane];
            float ss = v0*as0 + v1*as1;
            float dd = v0*ad0 + v1*ad1;
            #pragma unroll
            for (int off = 16; off; off >>= 1) {
                ss += __shfl_xor_sync(0xffffffffu, ss, off);
                dd += __shfl_xor_sync(0xffffffffu, dd, off);
            }
            if (lane == 0) { ssrc[n] = ss; sd[n] = dd; }
        }
    }
    sp[tid] = tid;
    __syncthreads();

    for (int k = 2; k <= 512; k <<= 1) {
        for (int j = k >> 1; j > 0; j >>= 1) {
            int ixj = tid ^ j;
            if (ixj > tid) {
                float a = sd[tid], c = sd[ixj];
                bool up = ((tid & k) == 0);
                if ((a > c) == up) {
                    sd[tid] = c; sd[ixj] = a;
                    int t2 = sp[tid]; sp[tid] = sp[ixj]; sp[ixj] = t2;
                }
            }
            __syncthreads();
        }
    }
    { float d = sd[tid]; Bv[tid] = expf(d); bv[tid] = expf(0.2f*d); }
    cnt[tid] = 0; if (tid == 0) cnt[512] = 0;
    __syncthreads();

    if (tid < 16) {
        int which = tid >> 3, sg = tid & 7; float acc = 0.f;
        for (int u = 0; u < 64; u++) { int t = sg*64+u; acc += which ? Bv[t] : bv[t]; }
        ztot[tid] = acc;
    }
    __syncthreads();
    if (tid < 16) {
        int which = tid >> 3, sg = tid & 7; float acc = 0.f;
        if (!which) {
            for (int s2 = 0; s2 < sg; s2++) acc += ztot[s2];
            for (int u = 0; u < 64; u++) { int t = sg*64+u; zPb[t] = acc; acc += bv[t]; }
            if (sg == 7) zPb[512] = acc;
        } else {
            for (int s2 = sg+1; s2 < 8; s2++) acc += ztot[8+s2];
            for (int u = 63; u >= 0; u--) { int t = sg*64+u; acc += Bv[t]; zSB[t] = acc; }
            if (sg == 7) zSB[512] = 0.f;
        }
    }
    __syncthreads();

    {
        float s = ssrc[tid], thr = -s;
        int lo = 0, hi = 512;
        while (lo < hi) { int mid = (lo+hi) >> 1; if (sd[mid] > thr) hi = mid; else lo = mid+1; }
        int m = lo;
        float A = expf(s), af = expf(0.2f*s);
        rA[tid] = A; ra[tid] = af;
        rIZ[tid] = 1.f / (A*zSB[m] + af*zPb[m]);
        rm[tid] = m;
        atomicAdd(&cnt[m], 1);
    }
    __syncthreads();
    if (tid < 32) {
        int start = tid*17, end = min(513, start+17);
        int s = 0;
        for (int i = start; i < end; i++) s += cnt[i];
        int v = s;
        #pragma unroll
        for (int off = 1; off < 32; off <<= 1) {
            int u = __shfl_up_sync(0xffffffffu, v, off);
            if (tid >= off) v += u;
        }
        int run = v - s;
        for (int i = start; i < end; i++) { cum[i] = run; run += cnt[i]; }
        if (start < 513 && end == 513) cum[513] = run;
    }
    __syncthreads();
    cnt[tid] = 0; if (tid == 0) cnt[512] = 0;
    __syncthreads();
    { int m = rm[tid]; int pos = cum[m] + atomicAdd(&cnt[m], 1); rIdx[pos] = tid; }
    __syncthreads();

    int dim = tid & 63, seg = tid >> 6;
    {
        float tB = 0.f, tb = 0.f; int base = seg*64;
        #pragma unroll 8
        for (int u = 0; u < 64; u++) {
            int t = base + u; float w = sWh[sp[t]*64 + dim];
            tB += Bv[t]*w; tb += bv[t]*w;
        }
        segT[seg*64+dim] = tB; segT[512+seg*64+dim] = tb;
    }
    __syncthreads();
    {
        float* outB = g_x + (size_t)b*262144 + h*64;
        float accB = 0.f, accb = 0.f, tTb = 0.f;
        for (int s2 = 0; s2 < 8; s2++) {
            float vB = segT[s2*64+dim], vb = segT[512+s2*64+dim];
            if (s2 > seg) { accB += vB; accb += vb; }
            tTb += vb;
        }
        if (seg == 7) {
            for (int idx = cum[512]; idx < cum[513]; idx++) {
                int r = rIdx[idx];
                float val = (rA[r]*accB + ra[r]*(tTb - accb)) * rIZ[r];
                val = val > 0.f ? val : expf(val) - 1.f;
                outB[r*512 + dim] = val;
            }
        }
        int base = seg*64;
        for (int u = 63; u >= 0; u--) {
            int t = base + u;
            float w = sWh[sp[t]*64 + dim];
            accB += Bv[t]*w; accb += bv[t]*w;
            for (int idx = cum[t]; idx < cum[t+1]; idx++) {
                int r = rIdx[idx];
                float val = (rA[r]*accB + ra[r]*(tTb - accb)) * rIZ[r];
                val = val > 0.f ? val : expf(val) - 1.f;
                outB[r*512 + dim] = val;
            }
        }
    }
}

// ================= kC: Wh2 = x @ W_out (FFMA2, conflict-free), fused s2 dots =================
__global__ __launch_bounds__(256) void kC(const float* __restrict__ W_out,
                                          const float* __restrict__ aos,
                                          const float* __restrict__ aod) {
    __shared__ float sX[4096];
    __shared__ float sWt[4224];     // transposed [c][f], stride 66
    int b = blockIdx.x, nc = blockIdx.y;
    int tid = threadIdx.x;
    int tc = tid & 15, tr = tid >> 4;   // both 0..15
    int r0 = tr*4;
    const float* wp0 = sWt + (tc     )*66;
    const float* wp1 = sWt + (tc + 16)*66;
    const float* wp2 = sWt + (tc + 32)*66;
    const float* wp3 = sWt + (tc + 48)*66;
    ull acc[4][4];
    ull zero = pk2(0.f, 0.f);
    #pragma unroll
    for (int r = 0; r < 4; r++)
        #pragma unroll
        for (int c = 0; c < 4; c++) acc[r][c] = zero;
    const float* xbase = g_x + (size_t)(b*512 + nc*64)*512;
    for (int kc = 0; kc < 8; kc++) {
        __syncthreads();
        for (int i = tid; i < 1024; i += 256) {
            int n = i >> 4, c4 = i & 15;
            ((float4*)sX)[i] = *(const float4*)(xbase + (size_t)n*512 + kc*64 + c4*4);
        }
        for (int i = tid; i < 1024; i += 256) {
            float4 w = ((const float4*)(W_out + kc*4096))[i];
            int f = i >> 4, c4 = (i & 15)*4;
            sWt[(c4+0)*66 + f] = w.x;
            sWt[(c4+1)*66 + f] = w.y;
            sWt[(c4+2)*66 + f] = w.z;
            sWt[(c4+3)*66 + f] = w.w;
        }
        __syncthreads();
        #pragma unroll 8
        for (int f = 0; f < 64; f += 2) {
            ull x0 = *(const ull*)&sX[(r0+0)*64+f];
            ull x1 = *(const ull*)&sX[(r0+1)*64+f];
            ull x2 = *(const ull*)&sX[(r0+2)*64+f];
            ull x3 = *(const ull*)&sX[(r0+3)*64+f];
            ull w0 = *(const ull*)&wp0[f];
            ull w1 = *(const ull*)&wp1[f];
            ull w2 = *(const ull*)&wp2[f];
            ull w3 = *(const ull*)&wp3[f];
            acc[0][0] = fma2(x0,w0,acc[0][0]); acc[0][1] = fma2(x0,w1,acc[0][1]);
            acc[0][2] = fma2(x0,w2,acc[0][2]); acc[0][3] = fma2(x0,w3,acc[0][3]);
            acc[1][0] = fma2(x1,w0,acc[1][0]); acc[1][1] = fma2(x1,w1,acc[1][1]);
            acc[1][2] = fma2(x1,w2,acc[1][2]); acc[1][3] = fma2(x1,w3,acc[1][3]);
            acc[2][0] = fma2(x2,w0,acc[2][0]); acc[2][1] = fma2(x2,w1,acc[2][1]);
            acc[2][2] = fma2(x2,w2,acc[2][2]); acc[2][3] = fma2(x2,w3,acc[2][3]);
            acc[3][0] = fma2(x3,w0,acc[3][0]); acc[3][1] = fma2(x3,w1,acc[3][1]);
            acc[3][2] = fma2(x3,w2,acc[3][2]); acc[3][3] = fma2(x3,w3,acc[3][3]);
        }
    }
    __syncthreads();
    float* sO = sX;
    float vals[4][4];
    #pragma unroll
    for (int r = 0; r < 4; r++)
        #pragma unroll
        for (int c = 0; c < 4; c++) {
            float lo, hi; upk2(acc[r][c], lo, hi);
            vals[r][c] = lo + hi;
        }
    #pragma unroll
    for (int r = 0; r < 4; r++)
        #pragma unroll
        for (int c = 0; c < 4; c++)
            sO[(r0+r)*64 + tc + 16*c] = vals[r][c];
    float* wo = g_Wh2 + (size_t)(b*512 + nc*64 + r0)*64;
    #pragma unroll
    for (int r = 0; r < 4; r++)
        #pragma unroll
        for (int c = 0; c < 4; c++)
            wo[r*64 + tc + 16*c] = vals[r][c];
    __syncthreads();
    {
        int w = tid >> 5, lane = tid & 31;
        float as0 = aos[lane], as1 = aos[32+lane];
        float ad0 = aod[lane], ad1 = aod[32+lane];
        for (int n = w*8; n < w*8+8; n++) {
            float v0 = sO[n*64+lane], v1 = sO[n*64+32+lane];
            float ss = v0*as0 + v1*as1;
            float dd = v0*ad0 + v1*ad1;
            #pragma unroll
            for (int off = 16; off; off >>= 1) {
                ss += __shfl_xor_sync(0xffffffffu, ss, off);
                dd += __shfl_xor_sync(0xffffffffu, dd, off);
            }
            if (lane == 0) {
                g_s2src[b*512 + nc*64 + n] = ss;
                g_s2dst[b*512 + nc*64 + n] = dd;
            }
        }
    }
}

// ================= kG2: GAT layer2 (per b, dim-quarter of 16) — R8 version =================
#define G2_SMEM_FLOATS (8192 + 3584 + 1536 + 1027 + 1024 + 1026 + 64)

__global__ __launch_bounds__(512) void kG2() {
    extern __shared__ float sm[];
    float* sWh  = sm;                 // 8192 : [n][16]
    float* sd   = sm + 8192;
    float* Bv   = sd + 512;
    float* bv   = Bv + 512;
    float* ssrc = bv + 512;
    float* rA   = ssrc + 512;
    float* ra   = rA + 512;
    float* rIZ  = ra + 512;
    int*   sp   = (int*)(rIZ + 512);
    int*   rIdx = sp + 512;
    int*   rm   = rIdx + 512;
    int*   cum  = rm + 512;
    int*   cnt  = cum + 514;
    float* segT = (float*)(cnt + 513);   // 1024
    float* zSB  = segT + 1024;
    float* zPb  = zSB + 513;
    float* ztot = zPb + 513;             // 64

    int tid = threadIdx.x;
    int b = blockIdx.x >> 2, q = blockIdx.x & 3;

    for (int i = tid; i < 2048; i += 512) {
        int n = i >> 2, c4 = i & 3;
        ((float4*)sWh)[i] = *(const float4*)(g_Wh2 + (size_t)b*32768 + n*64 + q*16 + c4*4);
    }
    sd[tid]   = g_s2dst[b*512 + tid];
    ssrc[tid] = g_s2src[b*512 + tid];
    sp[tid]   = tid;
    __syncthreads();

    for (int k = 2; k <= 512; k <<= 1) {
        for (int j = k >> 1; j > 0; j >>= 1) {
            int ixj = tid ^ j;
            if (ixj > tid) {
                float a = sd[tid], c = sd[ixj];
                bool up = ((tid & k) == 0);
                if ((a > c) == up) {
                    sd[tid] = c; sd[ixj] = a;
                    int t2 = sp[tid]; sp[tid] = sp[ixj]; sp[ixj] = t2;
                }
            }
            __syncthreads();
        }
    }
    { float d = sd[tid]; Bv[tid] = expf(d); bv[tid] = expf(0.2f*d); }
    cnt[tid] = 0; if (tid == 0) cnt[512] = 0;
    __syncthreads();

    if (tid < 64) {
        int which = tid >> 5, sg = tid & 31; float acc = 0.f;
        for (int u = 0; u < 16; u++) { int t = sg*16+u; acc += which ? Bv[t] : bv[t]; }
        ztot[which*32 + sg] = acc;
    }
    __syncthreads();
    if (tid < 64) {
        int which = tid >> 5, sg = tid & 31; float acc = 0.f;
        if (!which) {
            for (int s2 = 0; s2 < sg; s2++) acc += ztot[s2];
            for (int u = 0; u < 16; u++) { int t = sg*16+u; zPb[t] = acc; acc += bv[t]; }
            if (sg == 31) zPb[512] = acc;
        } else {
            for (int s2 = sg+1; s2 < 32; s2++) acc += ztot[32+s2];
            for (int u = 15; u >= 0; u--) { int t = sg*16+u; acc += Bv[t]; zSB[t] = acc; }
            if (sg == 31) zSB[512] = 0.f;
        }
    }
    __syncthreads();

    {
        float s = ssrc[tid], thr = -s;
        int lo = 0, hi = 512;
        while (lo < hi) { int mid = (lo+hi) >> 1; if (sd[mid] > thr) hi = mid; else lo = mid+1; }
        int m = lo;
        float A = expf(s), af = expf(0.2f*s);
        rA[tid] = A; ra[tid] = af;
        rIZ[tid] = 1.f / (A*zSB[m] + af*zPb[m]);
        rm[tid] = m;
        atomicAdd(&cnt[m], 1);
    }
    __syncthreads();
    if (tid < 32) {
        int start = tid*17, end = min(513, start+17);
        int s = 0;
        for (int i = start; i < end; i++) s += cnt[i];
        int v = s;
        #pragma unroll
        for (int off = 1; off < 32; off <<= 1) {
            int u = __shfl_up_sync(0xffffffffu, v, off);
            if (tid >= off) v += u;
        }
        int run = v - s;
        for (int i = start; i < end; i++) { cum[i] = run; run += cnt[i]; }
        if (start < 513 && end == 513) cum[513] = run;
    }
    __syncthreads();
    cnt[tid] = 0; if (tid == 0) cnt[512] = 0;
    __syncthreads();
    { int m = rm[tid]; int pos = cum[m] + atomicAdd(&cnt[m], 1); rIdx[pos] = tid; }
    __syncthreads();

    int dim = tid & 15, seg = tid >> 4;     // 32 segments x 16 dims
    {
        float tB = 0.f, tb = 0.f; int base = seg*16;
        #pragma unroll 8
        for (int u = 0; u < 16; u++) {
            int t = base + u; float w = sWh[sp[t]*16 + dim];
            tB += Bv[t]*w; tb += bv[t]*w;
        }
        segT[seg*16+dim] = tB; segT[512+seg*16+dim] = tb;
    }
    __syncthreads();
    {
        float* outB = g_z + (size_t)b*32768 + q*16;
        float accB = 0.f, accb = 0.f, tTb = 0.f;
        for (int s2 = 0; s2 < 32; s2++) {
            float vB = segT[s2*16+dim], vb = segT[512+s2*16+dim];
            if (s2 > seg) { accB += vB; accb += vb; }
            tTb += vb;
        }
        if (seg == 31) {
            for (int idx = cum[512]; idx < cum[513]; idx++) {
                int r = rIdx[idx];
                float val = (rA[r]*accB + ra[r]*(tTb - accb)) * rIZ[r];
                outB[r*64 + dim] = val;
            }
        }
        int base = seg*16;
        for (int u = 15; u >= 0; u--) {
            int t = base + u;
            float w = sWh[sp[t]*16 + dim];
            accB += Bv[t]*w; accb += bv[t]*w;
            for (int idx = cum[t]; idx < cum[t+1]; idx++) {
                int r = rIdx[idx];
                float val = (rA[r]*accB + ra[r]*(tTb - accb)) * rIZ[r];
                outB[r*64 + dim] = val;
            }
        }
    }
}

// ================= kE v4: fc1 split-K x split-rows streamer =================
__global__ __launch_bounds__(256) void kE(const float* __restrict__ fc1_w) {
    __shared__ __align__(16) ull sZd[16*128];   // packed (z,z), 16KB
    int tid = threadIdx.x;
    int split = blockIdx.x >> 1;
    int rh = blockIdx.x & 1;
    int k0 = split * 128;
    int cq = tid & 63;
    int rg = tid >> 6;                  // 0..3

    for (int i = tid; i < 2048; i += 256) {
        int r = i >> 7, k = i & 127;
        float v = g_z[(size_t)(rh*16 + r)*32768 + k0 + k];
        sZd[i] = pk2(v, v);
    }
    __syncthreads();

    ull acc[4][2];
    ull zero = pk2(0.f, 0.f);
    #pragma unroll
    for (int r = 0; r < 4; r++) { acc[r][0] = zero; acc[r][1] = zero; }

    const float* Wp = fc1_w + (size_t)k0*256 + cq*4;
    const ull* zp = &sZd[rg*4*128];
    #pragma unroll 4
    for (int k = 0; k < 128; k++) {
        float4 w = *(const float4*)(Wp + (size_t)k*256);
        ull w01 = pk2(w.x, w.y);
        ull w23 = pk2(w.z, w.w);
        #pragma unroll
        for (int r = 0; r < 4; r++) {
            ull zz = zp[r*128 + k];
            acc[r][0] = fma2(zz, w01, acc[r][0]);
            acc[r][1] = fma2(zz, w23, acc[r][1]);
        }
    }

    float* outp = g_part + (size_t)split*8192 + rh*16*256;
    #pragma unroll
    for (int r = 0; r < 4; r++) {
        float4 v;
        upk2(acc[r][0], v.x, v.y);
        upk2(acc[r][1], v.z, v.w);
        *(float4*)(outp + (rg*4 + r)*256 + cq*4) = v;
    }
}

// ================= kR: reduce 256 split-partials -> g_fc1acc =================
__global__ __launch_bounds__(256) void kR() {
    __shared__ float red[256];
    int b = blockIdx.x >> 3, cs = blockIdx.x & 7;
    int tid = threadIdx.x;
    int cl = tid & 31, sg = tid >> 5;
    const float* pp = g_part + (size_t)(sg*32)*8192 + b*256 + cs*32 + cl;
    float a = 0.f;
    #pragma unroll 8
    for (int s = 0; s < 32; s++) a += pp[(size_t)s*8192];
    red[tid] = a;
    __syncthreads();
    if (tid < 32) {
        float t = red[tid];
        #pragma unroll
        for (int j = 1; j < 8; j++) t += red[j*32 + tid];
        g_fc1acc[b*256 + cs*32 + tid] = t;
    }
}

// ================= kF: bias+relu, fc2, fc3, tanh =================
__global__ __launch_bounds__(256) void kF(const float* __restrict__ fc1_b, const float* __restrict__ fc2_w,
                   const float* __restrict__ fc2_b, const float* __restrict__ fc3_w,
                   const float* __restrict__ fc3_b, float* __restrict__ out) {
    int b = blockIdx.x; int tid = threadIdx.x;
    __shared__ float s1[256], s2[256];
    s1[tid] = fmaxf(g_fc1acc[b*256 + tid] + fc1_b[tid], 0.f);
    __syncthreads();
    float acc = fc2_b[tid];
    #pragma unroll 8
    for (int k2 = 0; k2 < 256; k2++) acc += s1[k2] * fc2_w[k2*256 + tid];
    s2[tid] = fmaxf(acc, 0.f);
    __syncthreads();
    if (tid < 4) {
        float a3 = fc3_b[tid];
        for (int k2 = 0; k2 < 256; k2++) a3 += s2[k2] * fc3_w[k2*4 + tid];
        out[b*4 + tid] = tanhf(a3);
    }
}

extern "C" void kernel_launch(void* const* d_in, const int* in_sizes, int n_in,
                              void* d_out, int out_size) {
    const float* state     = (const float*)d_in[0];
    const float* W_heads   = (const float*)d_in[1];
    const float* a_src     = (const float*)d_in[2];
    const float* a_dst     = (const float*)d_in[3];
    const float* W_out     = (const float*)d_in[4];
    const float* a_out_src = (const float*)d_in[5];
    const float* a_out_dst = (const float*)d_in[6];
    const float* fc1_w     = (const float*)d_in[7];
    const float* fc1_b     = (const float*)d_in[8];
    const float* fc2_w     = (const float*)d_in[9];
    const float* fc2_b     = (const float*)d_in[10];
    const float* fc3_w     = (const float*)d_in[11];
    const float* fc3_b     = (const float*)d_in[12];
    float* out = (float*)d_out;

    const int SM1 = G1_SMEM_FLOATS * 4;
    const int SM2 = G2_SMEM_FLOATS * 4;
    static int inited = 0;
    if (!inited) {
        cudaFuncSetAttribute(kG1, cudaFuncAttributeMaxDynamicSharedMemorySize, SM1);
        cudaFuncSetAttribute(kG2, cudaFuncAttributeMaxDynamicSharedMemorySize, SM2);
        inited = 1;
    }

    kG1<<<256, 512, SM1>>>(state, W_heads, a_src, a_dst);
    kC <<<dim3(32, 8), 256>>>(W_out, a_out_src, a_out_dst);
    kG2<<<128, 512, SM2>>>();
    kE <<<512, 256>>>(fc1_w);
    kR <<<256, 256>>>();
    kF <<<32, 256>>>(fc1_b, fc2_w, fc2_b, fc3_w, fc3_b, out);
}

// round 14
// speedup vs baseline: 1.2666x; 1.0059x over previous
#include <cuda_runtime.h>
#include <math.h>

#define BB 32
typedef unsigned long long ull;

// ---------------- scratch ----------------
__device__ float g_x    [BB*512*512];   // x[b][n][h*64+o]
__device__ float g_Wh2  [BB*512*64];
__device__ float g_s2src[BB*512];
__device__ float g_s2dst[BB*512];
__device__ float g_z    [BB*512*64];
__device__ float g_part [256*BB*256];   // fc1 split-K partials [split][b*256+c]
__device__ float g_fc1acc[BB*256];

// f32x2 packed helpers
__device__ __forceinline__ ull pk2(float lo, float hi) {
    ull r;
    asm("mov.b64 %0, {%1, %2};" : "=l"(r) : "f"(lo), "f"(hi));
    return r;
}
__device__ __forceinline__ void upk2(ull v, float& lo, float& hi) {
    asm("mov.b64 {%0, %1}, %2;" : "=f"(lo), "=f"(hi) : "l"(v));
}
__device__ __forceinline__ ull fma2(ull a, ull b, ull c) {
    ull d;
    asm("fma.rn.f32x2 %0, %1, %2, %3;" : "=l"(d) : "l"(a), "l"(b), "l"(c));
    return d;
}

// ================= kG1: fused feat@W_heads + GAT layer1 (per b,h) =================
// smem floats: sWh 32768 | work (sWt 4224 + sF 8192) | aux as R8
#define G1_SMEM_FLOATS (32768 + 12416 + 3584 + 1536 + 1027 + 1024 + 1026 + 16)

__global__ __launch_bounds__(512) void kG1(const float* __restrict__ state,
                                           const float* __restrict__ W_heads,
                                           const float* __restrict__ a_src,
                                           const float* __restrict__ a_dst) {
    extern __shared__ float sm[];
    float* sWh  = sm;                 // 32768
    float* work = sm + 32768;         // 12416
    float* sd   = sm + 45184;
    float* Bv   = sd + 512;
    float* bv   = Bv + 512;
    float* ssrc = bv + 512;
    float* rA   = ssrc + 512;
    float* ra   = rA + 512;
    float* rIZ  = ra + 512;
    int*   sp   = (int*)(rIZ + 512);
    int*   rIdx = sp + 512;
    int*   rm   = rIdx + 512;
    int*   cum  = rm + 512;           // 514
    int*   cnt  = cum + 514;          // 513
    float* segT = (float*)(cnt + 513);// 1024
    float* zSB  = segT + 1024;        // 513
    float* zPb  = zSB + 513;          // 513
    float* ztot = zPb + 513;          // 16

    int tid = threadIdx.x;
    int b = blockIdx.x >> 3, h = blockIdx.x & 7;
    float* sWt = work;                // transposed [c][f], stride 66 (4224)
    float* sF  = work + 4224;         // 8192 (128 rows x 64)

    // load & transpose W_heads[h]: sWt[c][f]
    for (int i = tid; i < 1024; i += 512) {
        float4 w = ((const float4*)(W_heads + h*4096))[i];
        int f = i >> 4, c4 = (i & 15)*4;
        sWt[(c4+0)*66 + f] = w.x;
        sWt[(c4+1)*66 + f] = w.y;
        sWt[(c4+2)*66 + f] = w.z;
        sWt[(c4+3)*66 + f] = w.w;
    }

    int tc = tid & 15, tr = tid >> 4;      // tc 0..15, tr 0..31
    int r0 = tr*4;
    const float* wp0 = sWt + (tc     )*66; // banks 2*tc — conflict-free
    const float* wp1 = sWt + (tc + 16)*66;
    const float* wp2 = sWt + (tc + 32)*66;
    const float* wp3 = sWt + (tc + 48)*66;

    for (int cc = 0; cc < 4; cc++) {
        __syncthreads();
        for (int i = tid; i < 2048; i += 512)
            ((float4*)sF)[i] = ((const float4*)(state + (size_t)b*32768 + cc*8192))[i];
        __syncthreads();
        ull acc[4][4];
        ull zero = pk2(0.f, 0.f);
        #pragma unroll
        for (int r = 0; r < 4; r++)
            #pragma unroll
            for (int c = 0; c < 4; c++) acc[r][c] = zero;
        #pragma unroll 8
        for (int f = 0; f < 64; f += 2) {
            ull x0 = *(const ull*)&sF[(r0+0)*64+f];
            ull x1 = *(const ull*)&sF[(r0+1)*64+f];
            ull x2 = *(const ull*)&sF[(r0+2)*64+f];
            ull x3 = *(const ull*)&sF[(r0+3)*64+f];
            ull w0 = *(const ull*)&wp0[f];
            ull w1 = *(const ull*)&wp1[f];
            ull w2 = *(const ull*)&wp2[f];
            ull w3 = *(const ull*)&wp3[f];
            acc[0][0] = fma2(x0,w0,acc[0][0]); acc[0][1] = fma2(x0,w1,acc[0][1]);
            acc[0][2] = fma2(x0,w2,acc[0][2]); acc[0][3] = fma2(x0,w3,acc[0][3]);
            acc[1][0] = fma2(x1,w0,acc[1][0]); acc[1][1] = fma2(x1,w1,acc[1][1]);
            acc[1][2] = fma2(x1,w2,acc[1][2]); acc[1][3] = fma2(x1,w3,acc[1][3]);
            acc[2][0] = fma2(x2,w0,acc[2][0]); acc[2][1] = fma2(x2,w1,acc[2][1]);
            acc[2][2] = fma2(x2,w2,acc[2][2]); acc[2][3] = fma2(x2,w3,acc[2][3]);
            acc[3][0] = fma2(x3,w0,acc[3][0]); acc[3][1] = fma2(x3,w1,acc[3][1]);
            acc[3][2] = fma2(x3,w2,acc[3][2]); acc[3][3] = fma2(x3,w3,acc[3][3]);
        }
        int nb = cc*128 + r0;
        #pragma unroll
        for (int r = 0; r < 4; r++) {
            #pragma unroll
            for (int c = 0; c < 4; c++) {
                float lo, hi; upk2(acc[r][c], lo, hi);
                sWh[(nb+r)*64 + tc + 16*c] = lo + hi;
            }
        }
    }
    __syncthreads();

    {
        int w = tid >> 5, lane = tid & 31;
        float as0 = a_src[h*64+lane], as1 = a_src[h*64+32+lane];
        float ad0 = a_dst[h*64+lane], ad1 = a_dst[h*64+32+lane];
        for (int n = w*32; n < w*32+32; n++) {
            float v0 = sWh[n*64+lane], v1 = sWh[n*64+32+lane];
            float ss = v0*as0 + v1*as1;
            float dd = v0*ad0 + v1*ad1;
            #pragma unroll
            for (int off = 16; off; off >>= 1) {
                ss += __shfl_xor_sync(0xffffffffu, ss, off);
                dd += __shfl_xor_sync(0xffffffffu, dd, off);
            }
            if (lane == 0) { ssrc[n] = ss; sd[n] = dd; }
        }
    }
    sp[tid] = tid;
    __syncthreads();

    for (int k = 2; k <= 512; k <<= 1) {
        for (int j = k >> 1; j > 0; j >>= 1) {
            int ixj = tid ^ j;
            if (ixj > tid) {
                float a = sd[tid], c = sd[ixj];
                bool up = ((tid & k) == 0);
                if ((a > c) == up) {
                    sd[tid] = c; sd[ixj] = a;
                    int t2 = sp[tid]; sp[tid] = sp[ixj]; sp[ixj] = t2;
                }
            }
            __syncthreads();
        }
    }
    { float d = sd[tid]; Bv[tid] = expf(d); bv[tid] = expf(0.2f*d); }
    cnt[tid] = 0; if (tid == 0) cnt[512] = 0;
    __syncthreads();

    if (tid < 16) {
        int which = tid >> 3, sg = tid & 7; float acc = 0.f;
        for (int u = 0; u < 64; u++) { int t = sg*64+u; acc += which ? Bv[t] : bv[t]; }
        ztot[tid] = acc;
    }
    __syncthreads();
    if (tid < 16) {
        int which = tid >> 3, sg = tid & 7; float acc = 0.f;
        if (!which) {
            for (int s2 = 0; s2 < sg; s2++) acc += ztot[s2];
            for (int u = 0; u < 64; u++) { int t = sg*64+u; zPb[t] = acc; acc += bv[t]; }
            if (sg == 7) zPb[512] = acc;
        } else {
            for (int s2 = sg+1; s2 < 8; s2++) acc += ztot[8+s2];
            for (int u = 63; u >= 0; u--) { int t = sg*64+u; acc += Bv[t]; zSB[t] = acc; }
            if (sg == 7) zSB[512] = 0.f;
        }
    }
    __syncthreads();

    {
        float s = ssrc[tid], thr = -s;
        int lo = 0, hi = 512;
        while (lo < hi) { int mid = (lo+hi) >> 1; if (sd[mid] > thr) hi = mid; else lo = mid+1; }
        int m = lo;
        float A = expf(s), af = expf(0.2f*s);
        rA[tid] = A; ra[tid] = af;
        rIZ[tid] = 1.f / (A*zSB[m] + af*zPb[m]);
        rm[tid] = m;
        atomicAdd(&cnt[m], 1);
    }
    __syncthreads();
    if (tid < 32) {
        int start = tid*17, end = min(513, start+17);
        int s = 0;
        for (int i = start; i < end; i++) s += cnt[i];
        int v = s;
        #pragma unroll
        for (int off = 1; off < 32; off <<= 1) {
            int u = __shfl_up_sync(0xffffffffu, v, off);
            if (tid >= off) v += u;
        }
        int run = v - s;
        for (int i = start; i < end; i++) { cum[i] = run; run += cnt[i]; }
        if (start < 513 && end == 513) cum[513] = run;
    }
    __syncthreads();
    cnt[tid] = 0; if (tid == 0) cnt[512] = 0;
    __syncthreads();
    { int m = rm[tid]; int pos = cum[m] + atomicAdd(&cnt[m], 1); rIdx[pos] = tid; }
    __syncthreads();

    int dim = tid & 63, seg = tid >> 6;
    {
        float tB = 0.f, tb = 0.f; int base = seg*64;
        #pragma unroll 8
        for (int u = 0; u < 64; u++) {
            int t = base + u; float w = sWh[sp[t]*64 + dim];
            tB += Bv[t]*w; tb += bv[t]*w;
        }
        segT[seg*64+dim] = tB; segT[512+seg*64+dim] = tb;
    }
    __syncthreads();
    {
        float* outB = g_x + (size_t)b*262144 + h*64;
        float accB = 0.f, accb = 0.f, tTb = 0.f;
        for (int s2 = 0; s2 < 8; s2++) {
            float vB = segT[s2*64+dim], vb = segT[512+s2*64+dim];
            if (s2 > seg) { accB += vB; accb += vb; }
            tTb += vb;
        }
        if (seg == 7) {
            for (int idx = cum[512]; idx < cum[513]; idx++) {
                int r = rIdx[idx];
                float val = (rA[r]*accB + ra[r]*(tTb - accb)) * rIZ[r];
                val = val > 0.f ? val : expf(val) - 1.f;
                outB[r*512 + dim] = val;
            }
        }
        int base = seg*64;
        for (int u = 63; u >= 0; u--) {
            int t = base + u;
            float w = sWh[sp[t]*64 + dim];
            accB += Bv[t]*w; accb += bv[t]*w;
            for (int idx = cum[t]; idx < cum[t+1]; idx++) {
                int r = rIdx[idx];
                float val = (rA[r]*accB + ra[r]*(tTb - accb)) * rIZ[r];
                val = val > 0.f ? val : expf(val) - 1.f;
                outB[r*512 + dim] = val;
            }
        }
    }
}

// ================= kC: Wh2 = x @ W_out (FFMA2, conflict-free), fused s2 dots =================
__global__ __launch_bounds__(256) void kC(const float* __restrict__ W_out,
                                          const float* __restrict__ aos,
                                          const float* __restrict__ aod) {
    __shared__ float sX[4096];
    __shared__ float sWt[4224];     // transposed [c][f], stride 66
    int b = blockIdx.x, nc = blockIdx.y;
    int tid = threadIdx.x;
    int tc = tid & 15, tr = tid >> 4;   // both 0..15
    int r0 = tr*4;
    const float* wp0 = sWt + (tc     )*66;
    const float* wp1 = sWt + (tc + 16)*66;
    const float* wp2 = sWt + (tc + 32)*66;
    const float* wp3 = sWt + (tc + 48)*66;
    ull acc[4][4];
    ull zero = pk2(0.f, 0.f);
    #pragma unroll
    for (int r = 0; r < 4; r++)
        #pragma unroll
        for (int c = 0; c < 4; c++) acc[r][c] = zero;
    const float* xbase = g_x + (size_t)(b*512 + nc*64)*512;
    for (int kc = 0; kc < 8; kc++) {
        __syncthreads();
        for (int i = tid; i < 1024; i += 256) {
            int n = i >> 4, c4 = i & 15;
            ((float4*)sX)[i] = *(const float4*)(xbase + (size_t)n*512 + kc*64 + c4*4);
        }
        for (int i = tid; i < 1024; i += 256) {
            float4 w = ((const float4*)(W_out + kc*4096))[i];
            int f = i >> 4, c4 = (i & 15)*4;
            sWt[(c4+0)*66 + f] = w.x;
            sWt[(c4+1)*66 + f] = w.y;
            sWt[(c4+2)*66 + f] = w.z;
            sWt[(c4+3)*66 + f] = w.w;
        }
        __syncthreads();
        #pragma unroll 8
        for (int f = 0; f < 64; f += 2) {
            ull x0 = *(const ull*)&sX[(r0+0)*64+f];
            ull x1 = *(const ull*)&sX[(r0+1)*64+f];
            ull x2 = *(const ull*)&sX[(r0+2)*64+f];
            ull x3 = *(const ull*)&sX[(r0+3)*64+f];
            ull w0 = *(const ull*)&wp0[f];
            ull w1 = *(const ull*)&wp1[f];
            ull w2 = *(const ull*)&wp2[f];
            ull w3 = *(const ull*)&wp3[f];
            acc[0][0] = fma2(x0,w0,acc[0][0]); acc[0][1] = fma2(x0,w1,acc[0][1]);
            acc[0][2] = fma2(x0,w2,acc[0][2]); acc[0][3] = fma2(x0,w3,acc[0][3]);
            acc[1][0] = fma2(x1,w0,acc[1][0]); acc[1][1] = fma2(x1,w1,acc[1][1]);
            acc[1][2] = fma2(x1,w2,acc[1][2]); acc[1][3] = fma2(x1,w3,acc[1][3]);
            acc[2][0] = fma2(x2,w0,acc[2][0]); acc[2][1] = fma2(x2,w1,acc[2][1]);
            acc[2][2] = fma2(x2,w2,acc[2][2]); acc[2][3] = fma2(x2,w3,acc[2][3]);
            acc[3][0] = fma2(x3,w0,acc[3][0]); acc[3][1] = fma2(x3,w1,acc[3][1]);
            acc[3][2] = fma2(x3,w2,acc[3][2]); acc[3][3] = fma2(x3,w3,acc[3][3]);
        }
    }
    __syncthreads();
    float* sO = sX;
    float vals[4][4];
    #pragma unroll
    for (int r = 0; r < 4; r++)
        #pragma unroll
        for (int c = 0; c < 4; c++) {
            float lo, hi; upk2(acc[r][c], lo, hi);
            vals[r][c] = lo + hi;
        }
    #pragma unroll
    for (int r = 0; r < 4; r++)
        #pragma unroll
        for (int c = 0; c < 4; c++)
            sO[(r0+r)*64 + tc + 16*c] = vals[r][c];
    float* wo = g_Wh2 + (size_t)(b*512 + nc*64 + r0)*64;
    #pragma unroll
    for (int r = 0; r < 4; r++)
        #pragma unroll
        for (int c = 0; c < 4; c++)
            wo[r*64 + tc + 16*c] = vals[r][c];
    __syncthreads();
    {
        int w = tid >> 5, lane = tid & 31;
        float as0 = aos[lane], as1 = aos[32+lane];
        float ad0 = aod[lane], ad1 = aod[32+lane];
        for (int n = w*8; n < w*8+8; n++) {
            float v0 = sO[n*64+lane], v1 = sO[n*64+32+lane];
            float ss = v0*as0 + v1*as1;
            float dd = v0*ad0 + v1*ad1;
            #pragma unroll
            for (int off = 16; off; off >>= 1) {
                ss += __shfl_xor_sync(0xffffffffu, ss, off);
                dd += __shfl_xor_sync(0xffffffffu, dd, off);
            }
            if (lane == 0) {
                g_s2src[b*512 + nc*64 + n] = ss;
                g_s2dst[b*512 + nc*64 + n] = dd;
            }
        }
    }
}

// ================= kG2: GAT layer2 (per b, dim-quarter of 16) — R8 version =================
#define G2_SMEM_FLOATS (8192 + 3584 + 1536 + 1027 + 1024 + 1026 + 64)

__global__ __launch_bounds__(512) void kG2() {
    extern __shared__ float sm[];
    float* sWh  = sm;                 // 8192 : [n][16]
    float* sd   = sm + 8192;
    float* Bv   = sd + 512;
    float* bv   = Bv + 512;
    float* ssrc = bv + 512;
    float* rA   = ssrc + 512;
    float* ra   = rA + 512;
    float* rIZ  = ra + 512;
    int*   sp   = (int*)(rIZ + 512);
    int*   rIdx = sp + 512;
    int*   rm   = rIdx + 512;
    int*   cum  = rm + 512;
    int*   cnt  = cum + 514;
    float* segT = (float*)(cnt + 513);   // 1024
    float* zSB  = segT + 1024;
    float* zPb  = zSB + 513;
    float* ztot = zPb + 513;             // 64

    int tid = threadIdx.x;
    int b = blockIdx.x >> 2, q = blockIdx.x & 3;

    for (int i = tid; i < 2048; i += 512) {
        int n = i >> 2, c4 = i & 3;
        ((float4*)sWh)[i] = *(const float4*)(g_Wh2 + (size_t)b*32768 + n*64 + q*16 + c4*4);
    }
    sd[tid]   = g_s2dst[b*512 + tid];
    ssrc[tid] = g_s2src[b*512 + tid];
    sp[tid]   = tid;
    __syncthreads();

    for (int k = 2; k <= 512; k <<= 1) {
        for (int j = k >> 1; j > 0; j >>= 1) {
            int ixj = tid ^ j;
            if (ixj > tid) {
                float a = sd[tid], c = sd[ixj];
                bool up = ((tid & k) == 0);
                if ((a > c) == up) {
                    sd[tid] = c; sd[ixj] = a;
                    int t2 = sp[tid]; sp[tid] = sp[ixj]; sp[ixj] = t2;
                }
            }
            __syncthreads();
        }
    }
    { float d = sd[tid]; Bv[tid] = expf(d); bv[tid] = expf(0.2f*d); }
    cnt[tid] = 0; if (tid == 0) cnt[512] = 0;
    __syncthreads();

    if (tid < 64) {
        int which = tid >> 5, sg = tid & 31; float acc = 0.f;
        for (int u = 0; u < 16; u++) { int t = sg*16+u; acc += which ? Bv[t] : bv[t]; }
        ztot[which*32 + sg] = acc;
    }
    __syncthreads();
    if (tid < 64) {
        int which = tid >> 5, sg = tid & 31; float acc = 0.f;
        if (!which) {
            for (int s2 = 0; s2 < sg; s2++) acc += ztot[s2];
            for (int u = 0; u < 16; u++) { int t = sg*16+u; zPb[t] = acc; acc += bv[t]; }
            if (sg == 31) zPb[512] = acc;
        } else {
            for (int s2 = sg+1; s2 < 32; s2++) acc += ztot[32+s2];
            for (int u = 15; u >= 0; u--) { int t = sg*16+u; acc += Bv[t]; zSB[t] = acc; }
            if (sg == 31) zSB[512] = 0.f;
        }
    }
    __syncthreads();

    {
        float s = ssrc[tid], thr = -s;
        int lo = 0, hi = 512;
        while (lo < hi) { int mid = (lo+hi) >> 1; if (sd[mid] > thr) hi = mid; else lo = mid+1; }
        int m = lo;
        float A = expf(s), af = expf(0.2f*s);
        rA[tid] = A; ra[tid] = af;
        rIZ[tid] = 1.f / (A*zSB[m] + af*zPb[m]);
        rm[tid] = m;
        atomicAdd(&cnt[m], 1);
    }
    __syncthreads();
    if (tid < 32) {
        int start = tid*17, end = min(513, start+17);
        int s = 0;
        for (int i = start; i < end; i++) s += cnt[i];
        int v = s;
        #pragma unroll
        for (int off = 1; off < 32; off <<= 1) {
            int u = __shfl_up_sync(0xffffffffu, v, off);
            if (tid >= off) v += u;
        }
        int run = v - s;
        for (int i = start; i < end; i++) { cum[i] = run; run += cnt[i]; }
        if (start < 513 && end == 513) cum[513] = run;
    }
    __syncthreads();
    cnt[tid] = 0; if (tid == 0) cnt[512] = 0;
    __syncthreads();
    { int m = rm[tid]; int pos = cum[m] + atomicAdd(&cnt[m], 1); rIdx[pos] = tid; }
    __syncthreads();

    int dim = tid & 15, seg = tid >> 4;     // 32 segments x 16 dims
    {
        float tB = 0.f, tb = 0.f; int base = seg*16;
        #pragma unroll 8
        for (int u = 0; u < 16; u++) {
            int t = base + u; float w = sWh[sp[t]*16 + dim];
            tB += Bv[t]*w; tb += bv[t]*w;
        }
        segT[seg*16+dim] = tB; segT[512+seg*16+dim] = tb;
    }
    __syncthreads();
    {
        float* outB = g_z + (size_t)b*32768 + q*16;
        float accB = 0.f, accb = 0.f, tTb = 0.f;
        for (int s2 = 0; s2 < 32; s2++) {
            float vB = segT[s2*16+dim], vb = segT[512+s2*16+dim];
            if (s2 > seg) { accB += vB; accb += vb; }
            tTb += vb;
        }
        if (seg == 31) {
            for (int idx = cum[512]; idx < cum[513]; idx++) {
                int r = rIdx[idx];
                float val = (rA[r]*accB + ra[r]*(tTb - accb)) * rIZ[r];
                outB[r*64 + dim] = val;
            }
        }
        int base = seg*16;
        for (int u = 15; u >= 0; u--) {
            int t = base + u;
            float w = sWh[sp[t]*16 + dim];
            accB += Bv[t]*w; accb += bv[t]*w;
            for (int idx = cum[t]; idx < cum[t+1]; idx++) {
                int r = rIdx[idx];
                float val = (rA[r]*accB + ra[r]*(tTb - accb)) * rIZ[r];
                outB[r*64 + dim] = val;
            }
        }
    }
}

// ================= kE v5: fc1 split-K streamer, transposed z, 8 rows/thread =================
// grid 256 (k-split of 128), block 256: tid&63 = column quad, tid>>6 = row-group of 8.
// z staged as sZT[k][row] dup-packed (row stride 34 -> 16B aligned, conflict-bounded).
// Per warp per k: 4 wf (LDG.128) + 4 wf (LDS.128 bcast) for 32 thread-FMA2s.
__global__ __launch_bounds__(256, 2) void kE(const float* __restrict__ fc1_w) {
    __shared__ __align__(16) ull sZT[128*34];   // 34816 B
    int tid = threadIdx.x;
    int split = blockIdx.x;
    int k0 = split * 128;
    int cq = tid & 63;
    int rg = tid >> 6;                  // 0..3 -> rows rg*8..rg*8+7

    // stage z transposed + dup-packed
    for (int i = tid; i < 4096; i += 256) {
        int r = i >> 7, k = i & 127;
        float v = g_z[(size_t)r*32768 + k0 + k];
        sZT[k*34 + r] = pk2(v, v);
    }
    __syncthreads();

    ull acc[8][2];
    ull zero = pk2(0.f, 0.f);
    #pragma unroll
    for (int j = 0; j < 8; j++) { acc[j][0] = zero; acc[j][1] = zero; }

    const float4* Wp = (const float4*)(fc1_w + (size_t)k0*256 + cq*4);
    const ull* zb = sZT + rg*8;
    #pragma unroll 4
    for (int k = 0; k < 128; k++) {
        float4 w = Wp[(size_t)k*64];
        ull w01 = pk2(w.x, w.y);
        ull w23 = pk2(w.z, w.w);
        const ulonglong2* zr = (const ulonglong2*)(zb + k*34);
        ulonglong2 z01 = zr[0];
        ulonglong2 z23 = zr[1];
        ulonglong2 z45 = zr[2];
        ulonglong2 z67 = zr[3];
        acc[0][0] = fma2(z01.x, w01, acc[0][0]); acc[0][1] = fma2(z01.x, w23, acc[0][1]);
        acc[1][0] = fma2(z01.y, w01, acc[1][0]); acc[1][1] = fma2(z01.y, w23, acc[1][1]);
        acc[2][0] = fma2(z23.x, w01, acc[2][0]); acc[2][1] = fma2(z23.x, w23, acc[2][1]);
        acc[3][0] = fma2(z23.y, w01, acc[3][0]); acc[3][1] = fma2(z23.y, w23, acc[3][1]);
        acc[4][0] = fma2(z45.x, w01, acc[4][0]); acc[4][1] = fma2(z45.x, w23, acc[4][1]);
        acc[5][0] = fma2(z45.y, w01, acc[5][0]); acc[5][1] = fma2(z45.y, w23, acc[5][1]);
        acc[6][0] = fma2(z67.x, w01, acc[6][0]); acc[6][1] = fma2(z67.x, w23, acc[6][1]);
        acc[7][0] = fma2(z67.y, w01, acc[7][0]); acc[7][1] = fma2(z67.y, w23, acc[7][1]);
    }

    float* outp = g_part + (size_t)split*8192;
    #pragma unroll
    for (int j = 0; j < 8; j++) {
        float4 v;
        upk2(acc[j][0], v.x, v.y);
        upk2(acc[j][1], v.z, v.w);
        *(float4*)(outp + (rg*8 + j)*256 + cq*4) = v;
    }
}

// ================= kR: reduce 256 split-partials -> g_fc1acc =================
__global__ __launch_bounds__(256) void kR() {
    __shared__ float red[256];
    int b = blockIdx.x >> 3, cs = blockIdx.x & 7;
    int tid = threadIdx.x;
    int cl = tid & 31, sg = tid >> 5;
    const float* pp = g_part + (size_t)(sg*32)*8192 + b*256 + cs*32 + cl;
    float a = 0.f;
    #pragma unroll 8
    for (int s = 0; s < 32; s++) a += pp[(size_t)s*8192];
    red[tid] = a;
    __syncthreads();
    if (tid < 32) {
        float t = red[tid];
        #pragma unroll
        for (int j = 1; j < 8; j++) t += red[j*32 + tid];
        g_fc1acc[b*256 + cs*32 + tid] = t;
    }
}

// ================= kF: bias+relu, fc2, fc3, tanh =================
__global__ __launch_bounds__(256) void kF(const float* __restrict__ fc1_b, const float* __restrict__ fc2_w,
                   const float* __restrict__ fc2_b, const float* __restrict__ fc3_w,
                   const float* __restrict__ fc3_b, float* __restrict__ out) {
    int b = blockIdx.x; int tid = threadIdx.x;
    __shared__ float s1[256], s2[256];
    s1[tid] = fmaxf(g_fc1acc[b*256 + tid] + fc1_b[tid], 0.f);
    __syncthreads();
    float acc = fc2_b[tid];
    #pragma unroll 8
    for (int k2 = 0; k2 < 256; k2++) acc += s1[k2] * fc2_w[k2*256 + tid];
    s2[tid] = fmaxf(acc, 0.f);
    __syncthreads();
    if (tid < 4) {
        float a3 = fc3_b[tid];
        for (int k2 = 0; k2 < 256; k2++) a3 += s2[k2] * fc3_w[k2*4 + tid];
        out[b*4 + tid] = tanhf(a3);
    }
}

extern "C" void kernel_launch(void* const* d_in, const int* in_sizes, int n_in,
                              void* d_out, int out_size) {
    const float* state     = (const float*)d_in[0];
    const float* W_heads   = (const float*)d_in[1];
    const float* a_src     = (const float*)d_in[2];
    const float* a_dst     = (const float*)d_in[3];
    const float* W_out     = (const float*)d_in[4];
    const float* a_out_src = (const float*)d_in[5];
    const float* a_out_dst = (const float*)d_in[6];
    const float* fc1_w     = (const float*)d_in[7];
    const float* fc1_b     = (const float*)d_in[8];
    const float* fc2_w     = (const float*)d_in[9];
    const float* fc2_b     = (const float*)d_in[10];
    const float* fc3_w     = (const float*)d_in[11];
    const float* fc3_b     = (const float*)d_in[12];
    float* out = (float*)d_out;

    const int SM1 = G1_SMEM_FLOATS * 4;
    const int SM2 = G2_SMEM_FLOATS * 4;
    static int inited = 0;
    if (!inited) {
        cudaFuncSetAttribute(kG1, cudaFuncAttributeMaxDynamicSharedMemorySize, SM1);
        cudaFuncSetAttribute(kG2, cudaFuncAttributeMaxDynamicSharedMemorySize, SM2);
        inited = 1;
    }

    kG1<<<256, 512, SM1>>>(state, W_heads, a_src, a_dst);
    kC <<<dim3(32, 8), 256>>>(W_out, a_out_src, a_out_dst);
    kG2<<<128, 512, SM2>>>();
    kE <<<256, 256>>>(fc1_w);
    kR <<<256, 256>>>();
    kF <<<32, 256>>>(fc1_b, fc2_w, fc2_b, fc3_w, fc3_b, out);
}